// round 1
// baseline (speedup 1.0000x reference)
#include <cuda_runtime.h>
#include <math.h>

#define B_BATCH 4
#define T_SEQ   4096
#define C_DIM   1024
#define HD      64
#define PAD     68        // smem row stride (floats), avoids bank conflicts, keeps 16B alignment
#define NTHREADS 256

// Scratch for Q/K/V projections (allocations are forbidden; __device__ globals are allowed)
__device__ float g_q[B_BATCH * T_SEQ * HD];
__device__ float g_k[B_BATCH * T_SEQ * HD];
__device__ float g_v[B_BATCH * T_SEQ * HD];

// ---------------------------------------------------------------------------
// Projection: out = x @ W   x:(16384,1024)  W:(1024,64)
// One block = 64 rows x 64 cols of one of {Q,K,V} (blockIdx.y selects W).
// 16x16 thread grid, 4x4 micro-tile per thread, fp32.
// ---------------------------------------------------------------------------
__global__ __launch_bounds__(NTHREADS) void proj_kernel(
    const float* __restrict__ x, const float* __restrict__ W0,
    const float* __restrict__ W1, const float* __restrict__ W2)
{
    __shared__ float xs[64][PAD];   // [row][c]  (broadcast scalar reads)
    __shared__ float ws[64][PAD];   // [c][h]    (float4 reads)
    const int tid = threadIdx.x;
    const int tx = tid & 15, ty = tid >> 4;
    const int r0 = blockIdx.x * 64;
    const float* W   = (blockIdx.y == 0) ? W0  : (blockIdx.y == 1 ? W1  : W2);
    float*       dst = (blockIdx.y == 0) ? g_q : (blockIdx.y == 1 ? g_k : g_v);

    float acc[4][4] = {};
    for (int c0 = 0; c0 < C_DIM; c0 += 64) {
        __syncthreads();
#pragma unroll
        for (int i = 0; i < 16; i++) {
            int idx = tid + i * NTHREADS;
            int rr = idx >> 6, cc = idx & 63;
            xs[rr][cc] = x[(size_t)(r0 + rr) * C_DIM + (c0 + cc)];
            ws[rr][cc] = W[(size_t)(c0 + rr) * HD + cc];
        }
        __syncthreads();
#pragma unroll 16
        for (int k = 0; k < 64; k++) {
            float4 bb = *(const float4*)&ws[k][4 * tx];
            float a[4];
#pragma unroll
            for (int i = 0; i < 4; i++) a[i] = xs[4 * ty + i][k];
#pragma unroll
            for (int i = 0; i < 4; i++) {
                acc[i][0] += a[i] * bb.x;
                acc[i][1] += a[i] * bb.y;
                acc[i][2] += a[i] * bb.z;
                acc[i][3] += a[i] * bb.w;
            }
        }
    }
#pragma unroll
    for (int i = 0; i < 4; i++)
#pragma unroll
        for (int j = 0; j < 4; j++)
            dst[(size_t)(r0 + 4 * ty + i) * HD + 4 * tx + j] = acc[i][j];
}

// ---------------------------------------------------------------------------
// Flash attention, fp32, BLOCK_M = BLOCK_N = 64, H = 64.
// Causal load balancing: each block handles query tiles m = bx and m = 63-bx,
// so every block does exactly 65 key-tile iterations.
// ---------------------------------------------------------------------------
__global__ __launch_bounds__(NTHREADS) void attn_kernel(float* __restrict__ out)
{
    extern __shared__ float smem[];
    float (*qs )[PAD] = (float (*)[PAD])(smem);                // [r][h]
    float (*kst)[PAD] = (float (*)[PAD])(smem + 1 * 64 * PAD); // [h][c]  (transposed K)
    float (*vs )[PAD] = (float (*)[PAD])(smem + 2 * 64 * PAD); // [j][h]
    float (*ps )[PAD] = (float (*)[PAD])(smem + 3 * 64 * PAD); // [r][j]

    const int tid = threadIdx.x;
    const int tx = tid & 15, ty = tid >> 4;
    const int b = blockIdx.y;
    const float* Q = g_q + (size_t)b * T_SEQ * HD;
    const float* K = g_k + (size_t)b * T_SEQ * HD;
    const float* V = g_v + (size_t)b * T_SEQ * HD;
    float* O = out + (size_t)b * T_SEQ * HD;

#pragma unroll 1
    for (int pass = 0; pass < 2; pass++) {
        const int m  = (pass == 0) ? (int)blockIdx.x : (63 - (int)blockIdx.x);
        const int q0 = m * 64;

        __syncthreads();
#pragma unroll
        for (int i = 0; i < 16; i++) {
            int idx = tid + i * NTHREADS;
            int rr = idx >> 6, hh = idx & 63;
            qs[rr][hh] = Q[(size_t)(q0 + rr) * HD + hh];
        }

        float m_i[4], l_i[4], o_acc[4][4];
#pragma unroll
        for (int i = 0; i < 4; i++) {
            m_i[i] = -1e30f; l_i[i] = 0.f;
#pragma unroll
            for (int j = 0; j < 4; j++) o_acc[i][j] = 0.f;
        }

#pragma unroll 1
        for (int n = 0; n <= m; n++) {
            const int k0 = n * 64;
            __syncthreads();   // (a) previous iter's kst/vs reads are done
#pragma unroll
            for (int i = 0; i < 16; i++) {
                int idx = tid + i * NTHREADS;
                int cc = idx >> 6, hh = idx & 63;
                kst[hh][cc] = K[(size_t)(k0 + cc) * HD + hh];
                vs[cc][hh]  = V[(size_t)(k0 + cc) * HD + hh];
            }
            __syncthreads();   // (b) tiles visible

            // ---- S = Q K^T ----
            float s[4][4] = {};
#pragma unroll 16
            for (int h = 0; h < 64; h++) {
                float4 bb = *(const float4*)&kst[h][4 * tx];
                float a[4];
#pragma unroll
                for (int i = 0; i < 4; i++) a[i] = qs[4 * ty + i][h];
#pragma unroll
                for (int i = 0; i < 4; i++) {
                    s[i][0] += a[i] * bb.x;
                    s[i][1] += a[i] * bb.y;
                    s[i][2] += a[i] * bb.z;
                    s[i][3] += a[i] * bb.w;
                }
            }

            // ---- scale + causal mask ----
            if (n == m) {
#pragma unroll
                for (int i = 0; i < 4; i++)
#pragma unroll
                    for (int j = 0; j < 4; j++) {
                        int qi = q0 + 4 * ty + i, kj = k0 + 4 * tx + j;
                        s[i][j] = (kj > qi) ? -1e30f : s[i][j] * 0.125f;
                    }
            } else {
#pragma unroll
                for (int i = 0; i < 4; i++)
#pragma unroll
                    for (int j = 0; j < 4; j++) s[i][j] *= 0.125f;
            }

            // ---- online softmax (row stats across the 16-lane tx group) ----
            float rmax[4];
#pragma unroll
            for (int i = 0; i < 4; i++)
                rmax[i] = fmaxf(fmaxf(s[i][0], s[i][1]), fmaxf(s[i][2], s[i][3]));
#pragma unroll
            for (int off = 1; off < 16; off <<= 1)
#pragma unroll
                for (int i = 0; i < 4; i++)
                    rmax[i] = fmaxf(rmax[i], __shfl_xor_sync(0xffffffffu, rmax[i], off));

            float alpha[4], rsum[4];
#pragma unroll
            for (int i = 0; i < 4; i++) {
                float mn = fmaxf(m_i[i], rmax[i]);
                alpha[i] = __expf(m_i[i] - mn);
                m_i[i] = mn;
                rsum[i] = 0.f;
            }
#pragma unroll
            for (int i = 0; i < 4; i++)
#pragma unroll
                for (int j = 0; j < 4; j++) {
                    s[i][j] = __expf(s[i][j] - m_i[i]);
                    rsum[i] += s[i][j];
                }
#pragma unroll
            for (int off = 1; off < 16; off <<= 1)
#pragma unroll
                for (int i = 0; i < 4; i++)
                    rsum[i] += __shfl_xor_sync(0xffffffffu, rsum[i], off);
#pragma unroll
            for (int i = 0; i < 4; i++) {
                l_i[i] = l_i[i] * alpha[i] + rsum[i];
#pragma unroll
                for (int j = 0; j < 4; j++) o_acc[i][j] *= alpha[i];
            }

            // ---- stage P to smem ----
#pragma unroll
            for (int i = 0; i < 4; i++)
                *(float4*)&ps[4 * ty + i][4 * tx] =
                    make_float4(s[i][0], s[i][1], s[i][2], s[i][3]);
            __syncthreads();   // (c) P visible

            // ---- O += P @ V ----
#pragma unroll 16
            for (int j = 0; j < 64; j++) {
                float4 bb = *(const float4*)&vs[j][4 * tx];
                float a[4];
#pragma unroll
                for (int i = 0; i < 4; i++) a[i] = ps[4 * ty + i][j];
#pragma unroll
                for (int i = 0; i < 4; i++) {
                    o_acc[i][0] += a[i] * bb.x;
                    o_acc[i][1] += a[i] * bb.y;
                    o_acc[i][2] += a[i] * bb.z;
                    o_acc[i][3] += a[i] * bb.w;
                }
            }
        }

        // ---- epilogue ----
#pragma unroll
        for (int i = 0; i < 4; i++) {
            float inv = 1.0f / l_i[i];
#pragma unroll
            for (int j = 0; j < 4; j++)
                O[(size_t)(q0 + 4 * ty + i) * HD + 4 * tx + j] = o_acc[i][j] * inv;
        }
    }
}

// ---------------------------------------------------------------------------
extern "C" void kernel_launch(void* const* d_in, const int* in_sizes, int n_in,
                              void* d_out, int out_size)
{
    const float* x  = (const float*)d_in[0];
    const float* Wq = (const float*)d_in[1];
    const float* Wk = (const float*)d_in[2];
    const float* Wv = (const float*)d_in[3];
    float* out = (float*)d_out;

    proj_kernel<<<dim3(B_BATCH * T_SEQ / 64, 3), NTHREADS>>>(x, Wq, Wk, Wv);

    const int attn_smem = 4 * 64 * PAD * sizeof(float);  // 69632 B
    cudaFuncSetAttribute(attn_kernel, cudaFuncAttributeMaxDynamicSharedMemorySize, attn_smem);
    attn_kernel<<<dim3(32, B_BATCH), NTHREADS, attn_smem>>>(out);
}

// round 2
// speedup vs baseline: 2.7348x; 2.7348x over previous
#include <cuda_runtime.h>
#include <math.h>

#define TSEQ 4096
#define CDIM 1024
#define HDIM 64
#define NB   4

// Scratch (allocations forbidden; __device__ globals allowed)
__device__ float g_q[NB * TSEQ * HDIM];
__device__ float g_k[NB * TSEQ * HDIM];
__device__ float g_v[NB * TSEQ * HDIM];

// ---------------------------------------------------------------------------
// helpers
// ---------------------------------------------------------------------------
__device__ __forceinline__ unsigned f2tf(float x) {
    unsigned u;
    asm("cvt.rna.tf32.f32 %0, %1;" : "=r"(u) : "f"(x));
    return u;
}
__device__ __forceinline__ float tf32r(float x) { return __uint_as_float(f2tf(x)); }
__device__ __forceinline__ unsigned fu(float x) { return __float_as_uint(x); }

// D = A(16x8, tf32, row) * B(8x8, tf32, col) + D   (fp32 accum)
__device__ __forceinline__ void mma8(float* d, const unsigned* a, const unsigned* b) {
    asm volatile(
        "mma.sync.aligned.m16n8k8.row.col.f32.tf32.tf32.f32 "
        "{%0,%1,%2,%3}, {%4,%5,%6,%7}, {%8,%9}, {%0,%1,%2,%3};"
        : "+f"(d[0]), "+f"(d[1]), "+f"(d[2]), "+f"(d[3])
        : "r"(a[0]), "r"(a[1]), "r"(a[2]), "r"(a[3]), "r"(b[0]), "r"(b[1]));
}

// ---------------------------------------------------------------------------
// Fused QKV projection: 128 rows of x per block, all three 64-col outputs.
// Warps: mw = w&3 (32 rows, 2 m-frags), nw = w>>2 (32 cols, 4 n-frags).
// ---------------------------------------------------------------------------
#define XPAD 68   // A-operand pad: (4*l4 + lm) distinct mod 32
#define WPAD 72   // B-operand pad: (8*lm + l4) distinct mod 32

__global__ __launch_bounds__(256, 1) void proj_kernel(
    const float* __restrict__ x, const float* __restrict__ W0,
    const float* __restrict__ W1, const float* __restrict__ W2)
{
    extern __shared__ float sm[];
    float* xs = sm;                      // [128][XPAD]
    float* ws = sm + 128 * XPAD;         // [3][64][WPAD]

    const int tid = threadIdx.x;
    const int lane = tid & 31, w = tid >> 5;
    const int mw = w & 3, nw = w >> 2;
    const int l4 = lane >> 2, lm = lane & 3;
    const int r0 = blockIdx.x * 128;

    float acc[3][2][4][4];
#pragma unroll
    for (int a = 0; a < 3; a++)
#pragma unroll
        for (int b = 0; b < 2; b++)
#pragma unroll
            for (int c = 0; c < 4; c++)
#pragma unroll
                for (int d = 0; d < 4; d++) acc[a][b][c][d] = 0.f;

#pragma unroll 1
    for (int c0 = 0; c0 < CDIM; c0 += 64) {
        __syncthreads();
        // x tile 128x64 (cvt to tf32 at store)
#pragma unroll
        for (int i = 0; i < 8; i++) {
            int idx = tid + i * 256;
            int row = idx >> 4, c = (idx & 15) << 2;
            float4 v = *(const float4*)&x[(size_t)(r0 + row) * CDIM + c0 + c];
            float4 o = make_float4(tf32r(v.x), tf32r(v.y), tf32r(v.z), tf32r(v.w));
            *(float4*)&xs[row * XPAD + c] = o;
        }
        // W tiles 3 x 64x64
#pragma unroll
        for (int i = 0; i < 12; i++) {
            int idx = tid + i * 256;
            int mat = idx >> 10, rem = idx & 1023;
            int kr = rem >> 4, c = (rem & 15) << 2;
            const float* W = (mat == 0) ? W0 : (mat == 1 ? W1 : W2);
            float4 v = *(const float4*)&W[(size_t)(c0 + kr) * HDIM + c];
            float4 o = make_float4(tf32r(v.x), tf32r(v.y), tf32r(v.z), tf32r(v.w));
            *(float4*)&ws[mat * 64 * WPAD + kr * WPAD + c] = o;
        }
        __syncthreads();

#pragma unroll
        for (int ks = 0; ks < 8; ks++) {
            unsigned af[2][4];
#pragma unroll
            for (int mf = 0; mf < 2; mf++) {
                const float* xr = &xs[(32 * mw + 16 * mf + l4) * XPAD + 8 * ks + lm];
                af[mf][0] = fu(xr[0]);
                af[mf][1] = fu(xr[8 * XPAD]);
                af[mf][2] = fu(xr[4]);
                af[mf][3] = fu(xr[8 * XPAD + 4]);
            }
#pragma unroll
            for (int mat = 0; mat < 3; mat++)
#pragma unroll
                for (int nf = 0; nf < 4; nf++) {
                    int n0 = 32 * nw + 8 * nf;
                    const float* wr = &ws[mat * 64 * WPAD + (8 * ks + lm) * WPAD + n0 + l4];
                    unsigned bb[2] = { fu(wr[0]), fu(wr[4 * WPAD]) };
#pragma unroll
                    for (int mf = 0; mf < 2; mf++) mma8(acc[mat][mf][nf], af[mf], bb);
                }
        }
    }

#pragma unroll
    for (int mat = 0; mat < 3; mat++) {
        float* dst = (mat == 0) ? g_q : (mat == 1 ? g_k : g_v);
#pragma unroll
        for (int mf = 0; mf < 2; mf++)
#pragma unroll
            for (int nf = 0; nf < 4; nf++) {
                int rg = r0 + 32 * mw + 16 * mf + l4;
                int col = 32 * nw + 8 * nf + 2 * lm;
                *(float2*)&dst[(size_t)rg * HDIM + col] =
                    make_float2(acc[mat][mf][nf][0], acc[mat][mf][nf][1]);
                *(float2*)&dst[(size_t)(rg + 8) * HDIM + col] =
                    make_float2(acc[mat][mf][nf][2], acc[mat][mf][nf][3]);
            }
    }
}

// ---------------------------------------------------------------------------
// Flash attention, tf32 mma, BM = BN = 64.
// Warps: mw = w&3 (16 rows, 1 m-frag), nw = w>>2 (32 cols, 4 n-frags).
// Paired query tiles (bx, 63-bx): each block does exactly 65 kv iterations.
// ---------------------------------------------------------------------------
#define KPAD 68
#define VPAD 72
#define PPAD 68
#define CFAC 0.18033688011112042f   // 0.125 * log2(e)

__global__ __launch_bounds__(256, 1) void attn_kernel(float* __restrict__ out)
{
    extern __shared__ float sm[];
    float* Ks   = sm;                         // [64][KPAD]   (key, h)
    float* Vs   = Ks + 64 * KPAD;             // [64][VPAD]   (key, h)
    float* Ps   = Vs + 64 * VPAD;             // [64][PPAD]   (row, key)
    float* redm = Ps + 64 * PPAD;             // [2][64]
    float* reds = redm + 128;                 // [2][64]

    const int tid = threadIdx.x;
    const int lane = tid & 31, w = tid >> 5;
    const int mw = w & 3, nw = w >> 2;
    const int l4 = lane >> 2, lm = lane & 3;
    const int rb = 16 * mw;
    const int b = blockIdx.y;

    const float* Q = g_q + (size_t)b * TSEQ * HDIM;
    const float* K = g_k + (size_t)b * TSEQ * HDIM;
    const float* V = g_v + (size_t)b * TSEQ * HDIM;
    float* O = out + (size_t)b * TSEQ * HDIM;

#pragma unroll 1
    for (int pass = 0; pass < 2; pass++) {
        const int m = (pass == 0) ? (int)blockIdx.x : (63 - (int)blockIdx.x);
        const int q0 = m * 64;

        // Q A-frags in registers (32 regs), tf32-rounded
        unsigned qf[8][4];
#pragma unroll
        for (int ks = 0; ks < 8; ks++) {
            qf[ks][0] = f2tf(Q[(size_t)(q0 + rb + l4) * HDIM + 8 * ks + lm]);
            qf[ks][1] = f2tf(Q[(size_t)(q0 + rb + 8 + l4) * HDIM + 8 * ks + lm]);
            qf[ks][2] = f2tf(Q[(size_t)(q0 + rb + l4) * HDIM + 8 * ks + 4 + lm]);
            qf[ks][3] = f2tf(Q[(size_t)(q0 + rb + 8 + l4) * HDIM + 8 * ks + 4 + lm]);
        }

        float oacc[4][4];
#pragma unroll
        for (int i = 0; i < 4; i++)
#pragma unroll
            for (int j = 0; j < 4; j++) oacc[i][j] = 0.f;
        float mrow[2] = { -1e30f, -1e30f };
        float lrow[2] = { 0.f, 0.f };

#pragma unroll 1
        for (int n = 0; n <= m; n++) {
            const int kb = n * 64;
            __syncthreads();  // S0: prior K/V/P reads complete
#pragma unroll
            for (int i = 0; i < 4; i++) {
                int idx = tid + i * 256;
                int key = idx >> 4, c = (idx & 15) << 2;
                float4 kv = *(const float4*)&K[(size_t)(kb + key) * HDIM + c];
                float4 vv = *(const float4*)&V[(size_t)(kb + key) * HDIM + c];
                *(float4*)&Ks[key * KPAD + c] =
                    make_float4(tf32r(kv.x), tf32r(kv.y), tf32r(kv.z), tf32r(kv.w));
                *(float4*)&Vs[key * VPAD + c] =
                    make_float4(tf32r(vv.x), tf32r(vv.y), tf32r(vv.z), tf32r(vv.w));
            }
            __syncthreads();  // S1: K,V visible

            // ---- S = Q K^T  (cols = keys) ----
            float s[4][4];
#pragma unroll
            for (int i = 0; i < 4; i++)
#pragma unroll
                for (int j = 0; j < 4; j++) s[i][j] = 0.f;
#pragma unroll
            for (int ks = 0; ks < 8; ks++)
#pragma unroll
                for (int nf = 0; nf < 4; nf++) {
                    int n0 = 32 * nw + 8 * nf;
                    const float* kr = &Ks[(n0 + l4) * KPAD + 8 * ks + lm];
                    unsigned bb[2] = { fu(kr[0]), fu(kr[4]) };
                    mma8(s[nf], qf[ks], bb);
                }

            // ---- scale (* 0.125*log2e) + causal mask on diagonal tile ----
            if (n == m) {
#pragma unroll
                for (int nf = 0; nf < 4; nf++) {
                    int lc = 32 * nw + 8 * nf + 2 * lm;
                    int lr1 = rb + l4, lr2 = lr1 + 8;
                    s[nf][0] = (lc     <= lr1) ? s[nf][0] * CFAC : -1e30f;
                    s[nf][1] = (lc + 1 <= lr1) ? s[nf][1] * CFAC : -1e30f;
                    s[nf][2] = (lc     <= lr2) ? s[nf][2] * CFAC : -1e30f;
                    s[nf][3] = (lc + 1 <= lr2) ? s[nf][3] * CFAC : -1e30f;
                }
            } else {
#pragma unroll
                for (int nf = 0; nf < 4; nf++)
#pragma unroll
                    for (int j = 0; j < 4; j++) s[nf][j] *= CFAC;
            }

            // ---- row max (local + 4-lane shfl + cross-warp via smem) ----
            float mx1 = -1e30f, mx2 = -1e30f;
#pragma unroll
            for (int nf = 0; nf < 4; nf++) {
                mx1 = fmaxf(mx1, fmaxf(s[nf][0], s[nf][1]));
                mx2 = fmaxf(mx2, fmaxf(s[nf][2], s[nf][3]));
            }
            mx1 = fmaxf(mx1, __shfl_xor_sync(0xffffffffu, mx1, 1));
            mx1 = fmaxf(mx1, __shfl_xor_sync(0xffffffffu, mx1, 2));
            mx2 = fmaxf(mx2, __shfl_xor_sync(0xffffffffu, mx2, 1));
            mx2 = fmaxf(mx2, __shfl_xor_sync(0xffffffffu, mx2, 2));
            if (lm == 0) {
                redm[nw * 64 + rb + l4] = mx1;
                redm[nw * 64 + rb + 8 + l4] = mx2;
            }
            __syncthreads();  // S2: redm visible
            float mn1 = fmaxf(mrow[0], fmaxf(mx1, redm[(1 ^ nw) * 64 + rb + l4]));
            float mn2 = fmaxf(mrow[1], fmaxf(mx2, redm[(1 ^ nw) * 64 + rb + 8 + l4]));
            float al1 = exp2f(mrow[0] - mn1);
            float al2 = exp2f(mrow[1] - mn2);
            mrow[0] = mn1; mrow[1] = mn2;

            // ---- p = exp2(s - m), partial sums, store P (tf32) ----
            float sum1 = 0.f, sum2 = 0.f;
#pragma unroll
            for (int nf = 0; nf < 4; nf++) {
                s[nf][0] = exp2f(s[nf][0] - mn1);
                s[nf][1] = exp2f(s[nf][1] - mn1);
                s[nf][2] = exp2f(s[nf][2] - mn2);
                s[nf][3] = exp2f(s[nf][3] - mn2);
                sum1 += s[nf][0] + s[nf][1];
                sum2 += s[nf][2] + s[nf][3];
            }
            sum1 += __shfl_xor_sync(0xffffffffu, sum1, 1);
            sum1 += __shfl_xor_sync(0xffffffffu, sum1, 2);
            sum2 += __shfl_xor_sync(0xffffffffu, sum2, 1);
            sum2 += __shfl_xor_sync(0xffffffffu, sum2, 2);
            if (lm == 0) {
                reds[nw * 64 + rb + l4] = sum1;
                reds[nw * 64 + rb + 8 + l4] = sum2;
            }
#pragma unroll
            for (int nf = 0; nf < 4; nf++) {
                int col = 32 * nw + 8 * nf + 2 * lm;
                *(float2*)&Ps[(rb + l4) * PPAD + col] =
                    make_float2(tf32r(s[nf][0]), tf32r(s[nf][1]));
                *(float2*)&Ps[(rb + 8 + l4) * PPAD + col] =
                    make_float2(tf32r(s[nf][2]), tf32r(s[nf][3]));
            }
            __syncthreads();  // S3: reds + P visible

            lrow[0] = lrow[0] * al1 + sum1 + reds[(1 ^ nw) * 64 + rb + l4];
            lrow[1] = lrow[1] * al2 + sum2 + reds[(1 ^ nw) * 64 + rb + 8 + l4];
#pragma unroll
            for (int nf = 0; nf < 4; nf++) {
                oacc[nf][0] *= al1; oacc[nf][1] *= al1;
                oacc[nf][2] *= al2; oacc[nf][3] *= al2;
            }

            // ---- O += P V  (cols = head dims) ----
#pragma unroll
            for (int ks = 0; ks < 8; ks++) {
                const float* pr = &Ps[(rb + l4) * PPAD + 8 * ks + lm];
                unsigned ap[4] = { fu(pr[0]), fu(pr[8 * PPAD]), fu(pr[4]), fu(pr[8 * PPAD + 4]) };
#pragma unroll
                for (int nf = 0; nf < 4; nf++) {
                    int n0 = 32 * nw + 8 * nf;
                    const float* vr = &Vs[(8 * ks + lm) * VPAD + n0 + l4];
                    unsigned bb[2] = { fu(vr[0]), fu(vr[4 * VPAD]) };
                    mma8(oacc[nf], ap, bb);
                }
            }
        }

        // ---- epilogue ----
        float inv1 = 1.0f / lrow[0];
        float inv2 = 1.0f / lrow[1];
#pragma unroll
        for (int nf = 0; nf < 4; nf++) {
            int col = 32 * nw + 8 * nf + 2 * lm;
            int r1 = q0 + rb + l4, r2 = r1 + 8;
            *(float2*)&O[(size_t)r1 * HDIM + col] =
                make_float2(oacc[nf][0] * inv1, oacc[nf][1] * inv1);
            *(float2*)&O[(size_t)r2 * HDIM + col] =
                make_float2(oacc[nf][2] * inv2, oacc[nf][3] * inv2);
        }
    }
}

// ---------------------------------------------------------------------------
extern "C" void kernel_launch(void* const* d_in, const int* in_sizes, int n_in,
                              void* d_out, int out_size)
{
    const float* x  = (const float*)d_in[0];
    const float* Wq = (const float*)d_in[1];
    const float* Wk = (const float*)d_in[2];
    const float* Wv = (const float*)d_in[3];
    float* out = (float*)d_out;

    const int proj_smem = (128 * XPAD + 3 * 64 * WPAD) * sizeof(float);   // 90112 B
    const int attn_smem = (64 * KPAD + 64 * VPAD + 64 * PPAD + 256) * sizeof(float); // 54272 B
    cudaFuncSetAttribute(proj_kernel, cudaFuncAttributeMaxDynamicSharedMemorySize, proj_smem);
    cudaFuncSetAttribute(attn_kernel, cudaFuncAttributeMaxDynamicSharedMemorySize, attn_smem);

    proj_kernel<<<NB * TSEQ / 128, 256, proj_smem>>>(x, Wq, Wk, Wv);
    attn_kernel<<<dim3(32, NB), 256, attn_smem>>>(out);
}

// round 3
// speedup vs baseline: 3.0840x; 1.1277x over previous
#include <cuda_runtime.h>
#include <math.h>

#define TSEQ 4096
#define CDIM 1024
#define HDIM 64
#define NB   4

__device__ float g_q[NB * TSEQ * HDIM];
__device__ float g_k[NB * TSEQ * HDIM];
__device__ float g_v[NB * TSEQ * HDIM];

__device__ __forceinline__ unsigned f2tf(float x) {
    unsigned u;
    asm("cvt.rna.tf32.f32 %0, %1;" : "=r"(u) : "f"(x));
    return u;
}
__device__ __forceinline__ float tf32r(float x) { return __uint_as_float(f2tf(x)); }
__device__ __forceinline__ unsigned fu(float x) { return __float_as_uint(x); }

__device__ __forceinline__ void mma8(float* d, const unsigned* a, const unsigned* b) {
    asm volatile(
        "mma.sync.aligned.m16n8k8.row.col.f32.tf32.tf32.f32 "
        "{%0,%1,%2,%3}, {%4,%5,%6,%7}, {%8,%9}, {%0,%1,%2,%3};"
        : "+f"(d[0]), "+f"(d[1]), "+f"(d[2]), "+f"(d[3])
        : "r"(a[0]), "r"(a[1]), "r"(a[2]), "r"(a[3]), "r"(b[0]), "r"(b[1]));
}

// ---------------------------------------------------------------------------
// Fused QKV projection (unchanged from round 2 — ~43us, near tf32 smem limit)
// ---------------------------------------------------------------------------
#define XPAD 68
#define WPAD 72

__global__ __launch_bounds__(256, 1) void proj_kernel(
    const float* __restrict__ x, const float* __restrict__ W0,
    const float* __restrict__ W1, const float* __restrict__ W2)
{
    extern __shared__ float sm[];
    float* xs = sm;
    float* ws = sm + 128 * XPAD;

    const int tid = threadIdx.x;
    const int lane = tid & 31, w = tid >> 5;
    const int mw = w & 3, nw = w >> 2;
    const int l4 = lane >> 2, lm = lane & 3;
    const int r0 = blockIdx.x * 128;

    float acc[3][2][4][4];
#pragma unroll
    for (int a = 0; a < 3; a++)
#pragma unroll
        for (int b = 0; b < 2; b++)
#pragma unroll
            for (int c = 0; c < 4; c++)
#pragma unroll
                for (int d = 0; d < 4; d++) acc[a][b][c][d] = 0.f;

#pragma unroll 1
    for (int c0 = 0; c0 < CDIM; c0 += 64) {
        __syncthreads();
#pragma unroll
        for (int i = 0; i < 8; i++) {
            int idx = tid + i * 256;
            int row = idx >> 4, c = (idx & 15) << 2;
            float4 v = *(const float4*)&x[(size_t)(r0 + row) * CDIM + c0 + c];
            *(float4*)&xs[row * XPAD + c] =
                make_float4(tf32r(v.x), tf32r(v.y), tf32r(v.z), tf32r(v.w));
        }
#pragma unroll
        for (int i = 0; i < 12; i++) {
            int idx = tid + i * 256;
            int mat = idx >> 10, rem = idx & 1023;
            int kr = rem >> 4, c = (rem & 15) << 2;
            const float* W = (mat == 0) ? W0 : (mat == 1 ? W1 : W2);
            float4 v = *(const float4*)&W[(size_t)(c0 + kr) * HDIM + c];
            *(float4*)&ws[mat * 64 * WPAD + kr * WPAD + c] =
                make_float4(tf32r(v.x), tf32r(v.y), tf32r(v.z), tf32r(v.w));
        }
        __syncthreads();

#pragma unroll
        for (int ks = 0; ks < 8; ks++) {
            unsigned af[2][4];
#pragma unroll
            for (int mf = 0; mf < 2; mf++) {
                const float* xr = &xs[(32 * mw + 16 * mf + l4) * XPAD + 8 * ks + lm];
                af[mf][0] = fu(xr[0]);
                af[mf][1] = fu(xr[8 * XPAD]);
                af[mf][2] = fu(xr[4]);
                af[mf][3] = fu(xr[8 * XPAD + 4]);
            }
#pragma unroll
            for (int mat = 0; mat < 3; mat++)
#pragma unroll
                for (int nf = 0; nf < 4; nf++) {
                    int n0 = 32 * nw + 8 * nf;
                    const float* wr = &ws[mat * 64 * WPAD + (8 * ks + lm) * WPAD + n0 + l4];
                    unsigned bb[2] = { fu(wr[0]), fu(wr[4 * WPAD]) };
#pragma unroll
                    for (int mf = 0; mf < 2; mf++) mma8(acc[mat][mf][nf], af[mf], bb);
                }
        }
    }

#pragma unroll
    for (int mat = 0; mat < 3; mat++) {
        float* dst = (mat == 0) ? g_q : (mat == 1 ? g_k : g_v);
#pragma unroll
        for (int mf = 0; mf < 2; mf++)
#pragma unroll
            for (int nf = 0; nf < 4; nf++) {
                int rg = r0 + 32 * mw + 16 * mf + l4;
                int col = 32 * nw + 8 * nf + 2 * lm;
                *(float2*)&dst[(size_t)rg * HDIM + col] =
                    make_float2(acc[mat][mf][nf][0], acc[mat][mf][nf][1]);
                *(float2*)&dst[(size_t)(rg + 8) * HDIM + col] =
                    make_float2(acc[mat][mf][nf][2], acc[mat][mf][nf][3]);
            }
    }
}

// ---------------------------------------------------------------------------
// Flash attention: double-buffered K/V with LDG prefetch, named pair barriers.
// ---------------------------------------------------------------------------
#define KPAD 68
#define VPAD 72
#define PPAD 68
#define CFAC 0.18033688011112042f   // 0.125 * log2(e)

__global__ __launch_bounds__(256, 1) void attn_kernel(float* __restrict__ out)
{
    extern __shared__ float sm[];
    float* Ks   = sm;                          // [2][64*KPAD]
    float* Vs   = Ks + 2 * 64 * KPAD;          // [2][64*VPAD]
    float* Ps   = Vs + 2 * 64 * VPAD;          // [64*PPAD]
    float* redm = Ps + 64 * PPAD;              // [2][64]
    float* reds = redm + 128;                  // [2][64]

    const int tid = threadIdx.x;
    const int lane = tid & 31, w = tid >> 5;
    const int mw = w & 3, nw = w >> 2;
    const int l4 = lane >> 2, lm = lane & 3;
    const int rb = 16 * mw;
    const int b = blockIdx.y;
    const int ldr = tid >> 4;              // base load row (0..15)
    const int ldc = (tid & 15) << 2;       // load col

    const float* Q = g_q + (size_t)b * TSEQ * HDIM;
    const float* K = g_k + (size_t)b * TSEQ * HDIM;
    const float* V = g_v + (size_t)b * TSEQ * HDIM;
    float* O = out + (size_t)b * TSEQ * HDIM;

#pragma unroll 1
    for (int pass = 0; pass < 2; pass++) {
        const int m = (pass == 0) ? (int)blockIdx.x : (63 - (int)blockIdx.x);
        const int q0 = m * 64;

        __syncthreads();   // smem reuse across passes

        unsigned qf[8][4];
#pragma unroll
        for (int ks = 0; ks < 8; ks++) {
            qf[ks][0] = f2tf(Q[(size_t)(q0 + rb + l4) * HDIM + 8 * ks + lm]);
            qf[ks][1] = f2tf(Q[(size_t)(q0 + rb + 8 + l4) * HDIM + 8 * ks + lm]);
            qf[ks][2] = f2tf(Q[(size_t)(q0 + rb + l4) * HDIM + 8 * ks + 4 + lm]);
            qf[ks][3] = f2tf(Q[(size_t)(q0 + rb + 8 + l4) * HDIM + 8 * ks + 4 + lm]);
        }

        float oacc[4][4];
#pragma unroll
        for (int i = 0; i < 4; i++)
#pragma unroll
            for (int j = 0; j < 4; j++) oacc[i][j] = 0.f;
        float mrow[2] = { -1e30f, -1e30f };
        float lrow[2] = { 0.f, 0.f };

        // prefetch kv tile 0
        float4 kst[4], vst[4];
#pragma unroll
        for (int i = 0; i < 4; i++) {
            kst[i] = *(const float4*)&K[(size_t)(ldr + 16 * i) * HDIM + ldc];
            vst[i] = *(const float4*)&V[(size_t)(ldr + 16 * i) * HDIM + ldc];
        }

#pragma unroll 1
        for (int n = 0; n <= m; n++) {
            const int buf = n & 1;
            float* Kb = Ks + buf * 64 * KPAD;
            float* Vb = Vs + buf * 64 * VPAD;

            // commit prefetched tile (cvt to tf32 at store)
#pragma unroll
            for (int i = 0; i < 4; i++) {
                int row = ldr + 16 * i;
                *(float4*)&Kb[row * KPAD + ldc] =
                    make_float4(tf32r(kst[i].x), tf32r(kst[i].y), tf32r(kst[i].z), tf32r(kst[i].w));
                *(float4*)&Vb[row * VPAD + ldc] =
                    make_float4(tf32r(vst[i].x), tf32r(vst[i].y), tf32r(vst[i].z), tf32r(vst[i].w));
            }
            __syncthreads();   // tile visible; also fences buffer reuse

            // prefetch next tile (covered by this iteration's compute)
            if (n < m) {
                const size_t kb2 = (size_t)(n + 1) * 64;
#pragma unroll
                for (int i = 0; i < 4; i++) {
                    kst[i] = *(const float4*)&K[(kb2 + ldr + 16 * i) * HDIM + ldc];
                    vst[i] = *(const float4*)&V[(kb2 + ldr + 16 * i) * HDIM + ldc];
                }
            }

            // ---- S = Q K^T ----
            float s[4][4];
#pragma unroll
            for (int i = 0; i < 4; i++)
#pragma unroll
                for (int j = 0; j < 4; j++) s[i][j] = 0.f;
#pragma unroll
            for (int ks = 0; ks < 8; ks++)
#pragma unroll
                for (int nf = 0; nf < 4; nf++) {
                    int n0 = 32 * nw + 8 * nf;
                    const float* kr = &Kb[(n0 + l4) * KPAD + 8 * ks + lm];
                    unsigned bb[2] = { fu(kr[0]), fu(kr[4]) };
                    mma8(s[nf], qf[ks], bb);
                }

            // ---- scale + causal mask ----
            if (n == m) {
#pragma unroll
                for (int nf = 0; nf < 4; nf++) {
                    int lc = 32 * nw + 8 * nf + 2 * lm;
                    int lr1 = rb + l4, lr2 = lr1 + 8;
                    s[nf][0] = (lc     <= lr1) ? s[nf][0] * CFAC : -1e30f;
                    s[nf][1] = (lc + 1 <= lr1) ? s[nf][1] * CFAC : -1e30f;
                    s[nf][2] = (lc     <= lr2) ? s[nf][2] * CFAC : -1e30f;
                    s[nf][3] = (lc + 1 <= lr2) ? s[nf][3] * CFAC : -1e30f;
                }
            } else {
#pragma unroll
                for (int nf = 0; nf < 4; nf++)
#pragma unroll
                    for (int j = 0; j < 4; j++) s[nf][j] *= CFAC;
            }

            // ---- row max: quad shfl + pair exchange via named barrier ----
            float mx1 = -1e30f, mx2 = -1e30f;
#pragma unroll
            for (int nf = 0; nf < 4; nf++) {
                mx1 = fmaxf(mx1, fmaxf(s[nf][0], s[nf][1]));
                mx2 = fmaxf(mx2, fmaxf(s[nf][2], s[nf][3]));
            }
            mx1 = fmaxf(mx1, __shfl_xor_sync(0xffffffffu, mx1, 1));
            mx1 = fmaxf(mx1, __shfl_xor_sync(0xffffffffu, mx1, 2));
            mx2 = fmaxf(mx2, __shfl_xor_sync(0xffffffffu, mx2, 1));
            mx2 = fmaxf(mx2, __shfl_xor_sync(0xffffffffu, mx2, 2));
            if (lm == 0) {
                redm[nw * 64 + rb + l4] = mx1;
                redm[nw * 64 + rb + 8 + l4] = mx2;
            }
            asm volatile("bar.sync %0, 64;" :: "r"(1 + mw) : "memory");
            float mn1 = fmaxf(mrow[0], fmaxf(mx1, redm[(1 ^ nw) * 64 + rb + l4]));
            float mn2 = fmaxf(mrow[1], fmaxf(mx2, redm[(1 ^ nw) * 64 + rb + 8 + l4]));
            float al1 = exp2f(mrow[0] - mn1);
            float al2 = exp2f(mrow[1] - mn2);
            mrow[0] = mn1; mrow[1] = mn2;

            // ---- exp + partial sums + P store ----
            float sum1 = 0.f, sum2 = 0.f;
#pragma unroll
            for (int nf = 0; nf < 4; nf++) {
                s[nf][0] = exp2f(s[nf][0] - mn1);
                s[nf][1] = exp2f(s[nf][1] - mn1);
                s[nf][2] = exp2f(s[nf][2] - mn2);
                s[nf][3] = exp2f(s[nf][3] - mn2);
                sum1 += s[nf][0] + s[nf][1];
                sum2 += s[nf][2] + s[nf][3];
            }
            sum1 += __shfl_xor_sync(0xffffffffu, sum1, 1);
            sum1 += __shfl_xor_sync(0xffffffffu, sum1, 2);
            sum2 += __shfl_xor_sync(0xffffffffu, sum2, 1);
            sum2 += __shfl_xor_sync(0xffffffffu, sum2, 2);
            if (lm == 0) {
                reds[nw * 64 + rb + l4] = sum1;
                reds[nw * 64 + rb + 8 + l4] = sum2;
            }
#pragma unroll
            for (int nf = 0; nf < 4; nf++) {
                int col = 32 * nw + 8 * nf + 2 * lm;
                *(float2*)&Ps[(rb + l4) * PPAD + col] =
                    make_float2(tf32r(s[nf][0]), tf32r(s[nf][1]));
                *(float2*)&Ps[(rb + 8 + l4) * PPAD + col] =
                    make_float2(tf32r(s[nf][2]), tf32r(s[nf][3]));
            }
            asm volatile("bar.sync %0, 64;" :: "r"(1 + mw) : "memory");

            lrow[0] = lrow[0] * al1 + sum1 + reds[(1 ^ nw) * 64 + rb + l4];
            lrow[1] = lrow[1] * al2 + sum2 + reds[(1 ^ nw) * 64 + rb + 8 + l4];
#pragma unroll
            for (int nf = 0; nf < 4; nf++) {
                oacc[nf][0] *= al1; oacc[nf][1] *= al1;
                oacc[nf][2] *= al2; oacc[nf][3] *= al2;
            }

            // ---- O += P V ----
#pragma unroll
            for (int ks = 0; ks < 8; ks++) {
                const float* pr = &Ps[(rb + l4) * PPAD + 8 * ks + lm];
                unsigned ap[4] = { fu(pr[0]), fu(pr[8 * PPAD]), fu(pr[4]), fu(pr[8 * PPAD + 4]) };
#pragma unroll
                for (int nf = 0; nf < 4; nf++) {
                    int n0 = 32 * nw + 8 * nf;
                    const float* vr = &Vb[(8 * ks + lm) * VPAD + n0 + l4];
                    unsigned bb[2] = { fu(vr[0]), fu(vr[4 * VPAD]) };
                    mma8(oacc[nf], ap, bb);
                }
            }
        }

        // ---- epilogue ----
        float inv1 = 1.0f / lrow[0];
        float inv2 = 1.0f / lrow[1];
#pragma unroll
        for (int nf = 0; nf < 4; nf++) {
            int col = 32 * nw + 8 * nf + 2 * lm;
            int r1 = q0 + rb + l4, r2 = r1 + 8;
            *(float2*)&O[(size_t)r1 * HDIM + col] =
                make_float2(oacc[nf][0] * inv1, oacc[nf][1] * inv1);
            *(float2*)&O[(size_t)r2 * HDIM + col] =
                make_float2(oacc[nf][2] * inv2, oacc[nf][3] * inv2);
        }
    }
}

// ---------------------------------------------------------------------------
extern "C" void kernel_launch(void* const* d_in, const int* in_sizes, int n_in,
                              void* d_out, int out_size)
{
    const float* x  = (const float*)d_in[0];
    const float* Wq = (const float*)d_in[1];
    const float* Wk = (const float*)d_in[2];
    const float* Wv = (const float*)d_in[3];
    float* out = (float*)d_out;

    const int proj_smem = (128 * XPAD + 3 * 64 * WPAD) * sizeof(float);
    const int attn_smem = (2 * 64 * KPAD + 2 * 64 * VPAD + 64 * PPAD + 256) * sizeof(float);
    cudaFuncSetAttribute(proj_kernel, cudaFuncAttributeMaxDynamicSharedMemorySize, proj_smem);
    cudaFuncSetAttribute(attn_kernel, cudaFuncAttributeMaxDynamicSharedMemorySize, attn_smem);

    proj_kernel<<<NB * TSEQ / 128, 256, proj_smem>>>(x, Wq, Wk, Wv);
    attn_kernel<<<dim3(32, NB), 256, attn_smem>>>(out);
}